// round 14
// baseline (speedup 1.0000x reference)
#include <cuda_runtime.h>
#include <cstdint>

#define NT 2
#define NC 128
#define NH 96
#define NW 96
#define HW 9216        // 96*96
#define NQ 18432       // NT*HW
#define HEADS 4
#define HD 32
#define QSCALE 0.17677669529663687f

// attention tile: 32 wide x 8 high
#define TW 32
#define TH 8
#define HC 39          // TW + 7
#define HR 15          // TH + 7
#define HP 585         // HR*HC

typedef unsigned long long ull;

// ---------------- scratch ----------------
__device__ __align__(16) float g_dw[3][NT][NC][HW];          // depthwise results q/k/v
__device__ __align__(16) float g_qT[NT * HEADS * HW * HD];   // [t][h][pix][d]
__device__ __align__(16) float g_kT[NT * HEADS * HW * HD];   // [t][h][pix][d]
__device__ __align__(16) float g_vT[NT * HEADS * HW * HD];   // [t][h][pix][d]
__device__ __align__(16) float g_att[NC * NQ];               // [c][q]  channel-major
__device__ __align__(16) float g_WT[4][NC][NC];              // transposed weights [k][n]

// ---------------- f32x2 helpers ----------------
__device__ __forceinline__ ull pk2(float lo, float hi) {
    ull r;
    asm("mov.b64 %0, {%1, %2};" : "=l"(r) : "f"(lo), "f"(hi));
    return r;
}
__device__ __forceinline__ void upk2(ull v, float& lo, float& hi) {
    asm("mov.b64 {%0, %1}, %2;" : "=f"(lo), "=f"(hi) : "l"(v));
}
__device__ __forceinline__ void fma2(ull& d, ull a, ull b) {
    asm("fma.rn.f32x2 %0, %1, %2, %0;" : "+l"(d) : "l"(a), "l"(b));
}
__device__ __forceinline__ int refl(int i) {
    i = (i < 0) ? -i : i;
    return (i > 95) ? 190 - i : i;
}

// ---------------- kernel 0: transpose weights into [k][n] ----------------
__global__ __launch_bounds__(256) void wt_kernel(
    const float* __restrict__ w0, const float* __restrict__ w1,
    const float* __restrict__ w2, const float* __restrict__ w3)
{
    __shared__ float tile[32][33];
    const float* srcs[4] = {w0, w1, w2, w3};
    int m = blockIdx.y;
    const float* W = srcs[m];
    int tr = blockIdx.x >> 2, tc = blockIdx.x & 3;   // 4x4 tiles of 32x32
    int tx = threadIdx.x & 31, ty = threadIdx.x >> 5;
#pragma unroll
    for (int i = 0; i < 4; i++)
        tile[ty * 4 + i][tx] = W[(tr * 32 + ty * 4 + i) * NC + tc * 32 + tx];
    __syncthreads();
#pragma unroll
    for (int i = 0; i < 4; i++)
        g_WT[m][tc * 32 + ty * 4 + i][tr * 32 + tx] = tile[tx][ty * 4 + i];
}

// ---------------- kernel 1: depthwise 3x3, zero-pad SAME ----------------
__global__ __launch_bounds__(256) void dw_kernel(
    const float* __restrict__ vid,
    const float* __restrict__ wq, const float* __restrict__ wk,
    const float* __restrict__ wv)
{
    int tid = threadIdx.x;
    int tx = tid & 31, ty = tid >> 5;
    int tilec = (blockIdx.x % 3) * 32, tiler = (blockIdx.x / 3) * 32;
    int t = blockIdx.y, cg = blockIdx.z;
    int gj = tilec + tx;
    int r0 = tiler + ty * 4;

    for (int cc = 0; cc < 8; cc++) {
        int c = cg * 8 + cc;
        const float* xp = vid + (t * NC + c) * HW;
        float x[6][3];
#pragma unroll
        for (int rr = 0; rr < 6; rr++) {
            int yy = r0 + rr - 1;
            bool yok = (yy >= 0 && yy < NH);
#pragma unroll
            for (int jj = 0; jj < 3; jj++) {
                int xxc = gj + jj - 1;
                x[rr][jj] = (yok && xxc >= 0 && xxc < NW) ? xp[yy * NW + xxc] : 0.f;
            }
        }
        float wqr[9], wkr[9], wvr[9];
#pragma unroll
        for (int i = 0; i < 9; i++) {
            wqr[i] = wq[c * 9 + i]; wkr[i] = wk[c * 9 + i]; wvr[i] = wv[c * 9 + i];
        }
#pragma unroll
        for (int p = 0; p < 4; p++) {
            float sq = 0.f, sk = 0.f, sv = 0.f;
#pragma unroll
            for (int ky = 0; ky < 3; ky++)
#pragma unroll
                for (int kx = 0; kx < 3; kx++) {
                    float xv = x[p + ky][kx];
                    sq = fmaf(xv, wqr[ky * 3 + kx], sq);
                    sk = fmaf(xv, wkr[ky * 3 + kx], sk);
                    sv = fmaf(xv, wvr[ky * 3 + kx], sv);
                }
            int pix = (r0 + p) * NW + gj;
            g_dw[0][t][c][pix] = sq;
            g_dw[1][t][c][pix] = sk;
            g_dw[2][t][c][pix] = sv;
        }
    }
}

// ================= GEMM core (BM=128, 2 blocks/SM) — R9 best =================
__device__ __forceinline__ void gemm_core(
    const float* __restrict__ WT, const float* __restrict__ bias,
    const float* __restrict__ X, int xstride, int x0,
    float (&va)[4][16])
{
    extern __shared__ float sm[];
    float* Ws = sm;                 // [128][128]
    float* Xs = sm + NC * NC;       // [2][16][128]
    const int tid = threadIdx.x;
    const int tm = tid & 31, tn = tid >> 5;
    const int n0 = tn * 16;

#pragma unroll
    for (int i = 0; i < 16; i++)
        reinterpret_cast<float4*>(Ws)[tid + i * 256] =
            reinterpret_cast<const float4*>(WT)[tid + i * 256];

    {
        int f0 = tid * 2;
#pragma unroll
        for (int j = 0; j < 2; j++) {
            int f = f0 + j, kk = f >> 5, m4 = f & 31;
            reinterpret_cast<float4*>(Xs)[f] =
                *reinterpret_cast<const float4*>(&X[(size_t)kk * xstride + x0 + m4 * 4]);
        }
    }
    __syncthreads();

    ull acc[4][8];
#pragma unroll
    for (int c = 0; c < 8; c++) {
        ull b = pk2(bias[n0 + 2 * c], bias[n0 + 2 * c + 1]);
#pragma unroll
        for (int i = 0; i < 4; i++) acc[i][c] = b;
    }

#pragma unroll 1
    for (int kc = 0; kc < 8; kc++) {
        float4 pre[2];
        if (kc < 7) {
            int f0 = tid * 2;
#pragma unroll
            for (int j = 0; j < 2; j++) {
                int f = f0 + j, kk = (kc + 1) * 16 + (f >> 5), m4 = f & 31;
                pre[j] = *reinterpret_cast<const float4*>(&X[(size_t)kk * xstride + x0 + m4 * 4]);
            }
        }
        const float* Xb = Xs + (kc & 1) * (16 * 128);
#pragma unroll
        for (int k = 0; k < 16; k++) {
            float4 a4 = *reinterpret_cast<const float4*>(&Xb[k * 128 + tm * 4]);
            ull ad0 = pk2(a4.x, a4.x), ad1 = pk2(a4.y, a4.y);
            ull ad2 = pk2(a4.z, a4.z), ad3 = pk2(a4.w, a4.w);
            const float* Wk = Ws + (kc * 16 + k) * 128 + n0;
#pragma unroll
            for (int c4 = 0; c4 < 4; c4++) {
                ulonglong2 bp = *reinterpret_cast<const ulonglong2*>(Wk + c4 * 4);
                fma2(acc[0][2 * c4 + 0], ad0, bp.x);
                fma2(acc[0][2 * c4 + 1], ad0, bp.y);
                fma2(acc[1][2 * c4 + 0], ad1, bp.x);
                fma2(acc[1][2 * c4 + 1], ad1, bp.y);
                fma2(acc[2][2 * c4 + 0], ad2, bp.x);
                fma2(acc[2][2 * c4 + 1], ad2, bp.y);
                fma2(acc[3][2 * c4 + 0], ad3, bp.x);
                fma2(acc[3][2 * c4 + 1], ad3, bp.y);
            }
        }
        if (kc < 7) {
            float* Xn = Xs + ((kc + 1) & 1) * (16 * 128);
            int f0 = tid * 2;
#pragma unroll
            for (int j = 0; j < 2; j++)
                reinterpret_cast<float4*>(Xn)[f0 + j] = pre[j];
            __syncthreads();
        }
    }

#pragma unroll
    for (int i = 0; i < 4; i++)
#pragma unroll
        for (int c = 0; c < 8; c++) upk2(acc[i][c], va[i][2 * c], va[i][2 * c + 1]);
}

// ---------------- kernel 2: pointwise 1x1 GEMM, pixel-major outputs ----------------
__global__ __launch_bounds__(256, 2) void pw_kernel(
    const float* __restrict__ bq_, const float* __restrict__ bk_,
    const float* __restrict__ bv_)
{
    int pix0 = blockIdx.x * 128;
    int t = blockIdx.y, proj = blockIdx.z;
    const float* bias = (proj == 0) ? bq_ : (proj == 1) ? bk_ : bv_;
    const float* X = &g_dw[proj][t][0][0];

    float va[4][16];
    gemm_core(&g_WT[proj][0][0], bias, X, HW, pix0, va);

    const int tn = threadIdx.x >> 5, tm = threadIdx.x & 31;
    const int n0 = tn * 16;

    if (proj == 0) {
#pragma unroll
        for (int i = 0; i < 4; i++)
#pragma unroll
            for (int c2 = 0; c2 < 16; c2++) va[i][c2] *= QSCALE;
    }

    float* dstT = (proj == 0) ? g_qT : (proj == 1) ? g_kT : g_vT;
    int h = n0 >> 5, dd = n0 & 31;
#pragma unroll
    for (int i = 0; i < 4; i++) {
        int pix = pix0 + tm * 4 + i;
        float* vp = &dstT[((size_t)(t * HEADS + h) * HW + pix) * HD + dd];
#pragma unroll
        for (int j = 0; j < 4; j++)
            *reinterpret_cast<float4*>(&vp[j * 4]) =
                make_float4(va[i][4 * j], va[i][4 * j + 1], va[i][4 * j + 2], va[i][4 * j + 3]);
    }
}

// ---------------- kernel 4: final projection GEMM ----------------
__global__ __launch_bounds__(256, 2) void proj_kernel(
    const float* __restrict__ pb, float* __restrict__ out)
{
    int q0 = blockIdx.x * 128;
    int t = q0 / HW, hw0 = q0 - t * HW;

    float va[4][16];
    gemm_core(&g_WT[3][0][0], pb, g_att, NQ, q0, va);

    const int tm = threadIdx.x & 31, tn = threadIdx.x >> 5;
    const int n0 = tn * 16;
#pragma unroll
    for (int c2 = 0; c2 < 16; c2++)
        *reinterpret_cast<float4*>(&out[(size_t)(t * NC + n0 + c2) * HW + hw0 + tm * 4]) =
            make_float4(va[0][c2], va[1][c2], va[2][c2], va[3][c2]);
}

// ---------------- kernel 3: non-local attention (chunked top-k, pixel-major inputs) ----------------
#define CEA(A, i, j) do { unsigned _a = A[i], _b = A[j]; \
    A[i] = (_a > _b) ? _a : _b; A[j] = (_a > _b) ? _b : _a; } while (0)

#define SORT8A(A, o) do { \
    CEA(A,o+0,o+1); CEA(A,o+2,o+3); CEA(A,o+4,o+5); CEA(A,o+6,o+7); \
    CEA(A,o+0,o+2); CEA(A,o+1,o+3); CEA(A,o+4,o+6); CEA(A,o+5,o+7); \
    CEA(A,o+1,o+2); CEA(A,o+5,o+6); \
    CEA(A,o+0,o+4); CEA(A,o+1,o+5); CEA(A,o+2,o+6); CEA(A,o+3,o+7); \
    CEA(A,o+2,o+4); CEA(A,o+3,o+5); \
    CEA(A,o+1,o+2); CEA(A,o+3,o+4); CEA(A,o+5,o+6); } while (0)

#define BM8A(A, o) do { \
    CEA(A,o+0,o+4); CEA(A,o+1,o+5); CEA(A,o+2,o+6); CEA(A,o+3,o+7); \
    CEA(A,o+0,o+2); CEA(A,o+1,o+3); CEA(A,o+4,o+6); CEA(A,o+5,o+7); \
    CEA(A,o+0,o+1); CEA(A,o+2,o+3); CEA(A,o+4,o+5); CEA(A,o+6,o+7); } while (0)

#define MERGE16A(A) do { \
    CEA(A,0,15); CEA(A,1,14); CEA(A,2,13); CEA(A,3,12); \
    CEA(A,4,11); CEA(A,5,10); CEA(A,6,9);  CEA(A,7,8); \
    BM8A(A,0); BM8A(A,8); } while (0)

#define SORTB16A(A) do { \
    CEA(A,0,8);  CEA(A,1,9);  CEA(A,2,10); CEA(A,3,11); \
    CEA(A,4,12); CEA(A,5,13); CEA(A,6,14); CEA(A,7,15); \
    BM8A(A,0); BM8A(A,8); } while (0)

__global__ __launch_bounds__(256, 2) void attn_kernel()
{
    extern __shared__ float sm[];
    const int tid = threadIdx.x;
    const int tx = tid & 31, ty = tid >> 5;
    const int tcx = (blockIdx.x % 3) * TW, trow = (blockIdx.x / 3) * TH;
    const int h = blockIdx.y, t = blockIdx.z;
    const size_t baseT = (size_t)(t * HEADS + h) * HW * HD;
    const int br = trow - 4, bc = tcx - 4;

    // stage reflected k halo from pixel-major source into d-quad layout: float4 [d4][lp]
    const float* kT = g_kT + baseT;
    for (int idx = tid; idx < 8 * HP; idx += 256) {
        int lp = idx >> 3, d4 = idx & 7;
        int lr = lp / HC, lc = lp - lr * HC;
        int ri = refl(br + lr), rj = refl(bc + lc);
        float4 kv = *reinterpret_cast<const float4*>(&kT[(size_t)(ri * NW + rj) * HD + d4 * 4]);
        reinterpret_cast<float4*>(sm)[d4 * HP + lp] = kv;
    }
    __syncthreads();

    const int gi = trow + ty, gj = tcx + tx;
    const int pix = gi * NW + gj;

    // q pairs: direct b64 loads from pixel-major q
    ull q2[16];
    {
        const ulonglong2* qp = reinterpret_cast<const ulonglong2*>(g_qT + baseT + (size_t)pix * HD);
#pragma unroll
        for (int j = 0; j < 8; j++) {
            ulonglong2 v = qp[j];
            q2[2 * j] = v.x;
            q2[2 * j + 1] = v.y;
        }
    }

    unsigned top[16];
    unsigned mxkey = 0;

#pragma unroll
    for (int ch = 0; ch < 4; ch++) {
        unsigned key[16];
#pragma unroll
        for (int a2 = 0; a2 < 2; a2++) {
            int arow = 2 * ch + a2;
#pragma unroll
            for (int b = 0; b < 8; b++) {
                int lp = (ty + arow) * HC + (tx + b);
                const ulonglong2* kp = reinterpret_cast<const ulonglong2*>(sm) + lp;
                ull s0 = 0ull, s1 = 0ull;
#pragma unroll
                for (int d4 = 0; d4 < 8; d4++) {
                    ulonglong2 kv = kp[d4 * HP];      // direct b64 pair
                    fma2(s0, q2[2 * d4],     kv.x);
                    fma2(s1, q2[2 * d4 + 1], kv.y);
                }
                float x0, x1, y0, y1;
                upk2(s0, x0, x1); upk2(s1, y0, y1);
                float s = (x0 + y0) + (x1 + y1);
                unsigned u = __float_as_uint(s);
                unsigned kk = (u & 0x80000000u) ? ~u : (u | 0x80000000u);
                key[a2 * 8 + b] = (kk & 0xFFFFFFC0u) | (unsigned)(arow * 8 + b);
            }
        }
        SORT8A(key, 0); SORT8A(key, 8);
        MERGE16A(key);
        if (ch == 0) {
            mxkey = key[0];
#pragma unroll
            for (int i = 0; i < 16; i++) top[i] = key[i];
        } else {
            if (key[0] > mxkey) mxkey = key[0];
#pragma unroll
            for (int i = 0; i < 16; i++) {
                unsigned b2 = key[15 - i];
                if (b2 > top[i]) top[i] = b2;
            }
            if (ch < 3) SORTB16A(top);
        }
    }
    __syncthreads();   // all k reads complete before overwrite

    // stage reflected v halo, pixel-major, XOR slot swizzle: float4 [lp][d4^(lp&7)]
    const float* vbase = g_vT + baseT;
    for (int idx = tid; idx < 8 * HP; idx += 256) {
        int lp = idx >> 3, d4 = idx & 7;
        int lr = lp / HC, lc = lp - lr * HC;
        int ri = refl(br + lr), rj = refl(bc + lc);
        float4 vv = *reinterpret_cast<const float4*>(&vbase[(size_t)(ri * NW + rj) * HD + d4 * 4]);
        reinterpret_cast<float4*>(sm)[lp * 8 + (d4 ^ (lp & 7))] = vv;
    }
    __syncthreads();

    unsigned mu = (mxkey & 0x80000000u) ? (mxkey ^ 0x80000000u) : ~mxkey;
    float mxv = __uint_as_float(mu);

    float wgt[16]; int lps[16];
    float wsum = 0.f;
#pragma unroll
    for (int p = 0; p < 16; p++) {
        unsigned kk = top[p];
        int ci = kk & 63;
        unsigned u = (kk & 0x80000000u) ? (kk ^ 0x80000000u) : ~kk;
        float e = __expf(__uint_as_float(u) - mxv);
        wsum += e;
        wgt[p] = e;
        lps[p] = (ty + (ci >> 3)) * HC + (tx + (ci & 7));
    }

    ull acc2[16];
#pragma unroll
    for (int c = 0; c < 16; c++) acc2[c] = 0ull;
#pragma unroll
    for (int p = 0; p < 16; p++) {
        int lp = lps[p];
        const ulonglong2* vp = reinterpret_cast<const ulonglong2*>(sm) + lp * 8;
        int sw = lp & 7;
        ull e2 = pk2(wgt[p], wgt[p]);
#pragma unroll
        for (int d4 = 0; d4 < 8; d4++) {
            ulonglong2 vv = vp[d4 ^ sw];
            fma2(acc2[2 * d4],     e2, vv.x);
            fma2(acc2[2 * d4 + 1], e2, vv.y);
        }
    }

    float inv = 1.f / wsum;
    const int qg = t * HW + pix;
#pragma unroll
    for (int c = 0; c < 16; c++) {
        float lo, hi;
        upk2(acc2[c], lo, hi);
        g_att[(size_t)(h * HD + 2 * c) * NQ + qg] = lo * inv;
        g_att[(size_t)(h * HD + 2 * c + 1) * NQ + qg] = hi * inv;
    }
}

// ---------------- launch ----------------
extern "C" void kernel_launch(void* const* d_in, const int* in_sizes, int n_in,
                              void* d_out, int out_size)
{
    const float* vid    = (const float*)d_in[0];
    const float* wq_dw  = (const float*)d_in[1];
    const float* wq_pw  = (const float*)d_in[2];
    const float* bq     = (const float*)d_in[3];
    const float* wk_dw  = (const float*)d_in[4];
    const float* wk_pw  = (const float*)d_in[5];
    const float* bk     = (const float*)d_in[6];
    const float* wv_dw  = (const float*)d_in[7];
    const float* wv_pw  = (const float*)d_in[8];
    const float* bv     = (const float*)d_in[9];
    const float* proj_w = (const float*)d_in[10];
    const float* proj_b = (const float*)d_in[11];
    float* out = (float*)d_out;

    const int attn_smem = 8 * HP * 16;                        // 74880
    const int gemm_smem = (NC * NC + 2 * 16 * NC) * (int)sizeof(float);  // 81920
    cudaFuncSetAttribute(attn_kernel, cudaFuncAttributeMaxDynamicSharedMemorySize, attn_smem);
    cudaFuncSetAttribute(pw_kernel, cudaFuncAttributeMaxDynamicSharedMemorySize, gemm_smem);
    cudaFuncSetAttribute(proj_kernel, cudaFuncAttributeMaxDynamicSharedMemorySize, gemm_smem);

    wt_kernel<<<dim3(16, 4), 256>>>(wq_pw, wk_pw, wv_pw, proj_w);
    dw_kernel<<<dim3(9, 2, 16), 256>>>(vid, wq_dw, wk_dw, wv_dw);
    pw_kernel<<<dim3(72, 2, 3), 256, gemm_smem>>>(bq, bk, bv);
    attn_kernel<<<dim3(36, 4, 2), 256, attn_smem>>>();
    proj_kernel<<<dim3(144, 1, 1), 256, gemm_smem>>>(proj_b, out);
}

// round 15
// speedup vs baseline: 1.5507x; 1.5507x over previous
#include <cuda_runtime.h>
#include <cstdint>

#define NT 2
#define NC 128
#define NH 96
#define NW 96
#define HW 9216        // 96*96
#define NQ 18432       // NT*HW
#define HEADS 4
#define HD 32
#define QSCALE 0.17677669529663687f

// attention tile: 32 wide x 8 high
#define TW 32
#define TH 8
#define HC 39          // TW + 7
#define HR 15          // TH + 7
#define HP 585         // HR*HC

typedef unsigned long long ull;

// ---------------- scratch ----------------
__device__ __align__(16) float g_dw[3][NT][NC][HW];          // depthwise results q/k/v
__device__ __align__(16) float g_q[NT * NC * HW];            // [t*128+c][pix]
__device__ __align__(16) float g_k[NT * NC * HW];            // [t*128+c][pix]
__device__ __align__(16) float g_vT[NT * HEADS * HW * HD];   // [t][h][pix][d]
__device__ __align__(16) float g_att[NC * NQ];               // [c][q]  channel-major
__device__ __align__(16) float g_WT[4][NC][NC];              // transposed weights [k][n]

// ---------------- f32x2 helpers ----------------
__device__ __forceinline__ ull pk2(float lo, float hi) {
    ull r;
    asm("mov.b64 %0, {%1, %2};" : "=l"(r) : "f"(lo), "f"(hi));
    return r;
}
__device__ __forceinline__ void upk2(ull v, float& lo, float& hi) {
    asm("mov.b64 {%0, %1}, %2;" : "=f"(lo), "=f"(hi) : "l"(v));
}
__device__ __forceinline__ void fma2(ull& d, ull a, ull b) {
    asm("fma.rn.f32x2 %0, %1, %2, %0;" : "+l"(d) : "l"(a), "l"(b));
}
__device__ __forceinline__ int refl(int i) {
    i = (i < 0) ? -i : i;
    return (i > 95) ? 190 - i : i;
}

// ---------------- kernel 0: transpose weights into [k][n] ----------------
__global__ __launch_bounds__(256) void wt_kernel(
    const float* __restrict__ w0, const float* __restrict__ w1,
    const float* __restrict__ w2, const float* __restrict__ w3)
{
    __shared__ float tile[32][33];
    const float* srcs[4] = {w0, w1, w2, w3};
    int m = blockIdx.y;
    const float* W = srcs[m];
    int tr = blockIdx.x >> 2, tc = blockIdx.x & 3;   // 4x4 tiles of 32x32
    int tx = threadIdx.x & 31, ty = threadIdx.x >> 5;
#pragma unroll
    for (int i = 0; i < 4; i++)
        tile[ty * 4 + i][tx] = W[(tr * 32 + ty * 4 + i) * NC + tc * 32 + tx];
    __syncthreads();
#pragma unroll
    for (int i = 0; i < 4; i++)
        g_WT[m][tc * 32 + ty * 4 + i][tr * 32 + tx] = tile[tx][ty * 4 + i];
}

// ---------------- kernel 1: depthwise 3x3, zero-pad SAME ----------------
__global__ __launch_bounds__(256) void dw_kernel(
    const float* __restrict__ vid,
    const float* __restrict__ wq, const float* __restrict__ wk,
    const float* __restrict__ wv)
{
    int tid = threadIdx.x;
    int tx = tid & 31, ty = tid >> 5;
    int tilec = (blockIdx.x % 3) * 32, tiler = (blockIdx.x / 3) * 32;
    int t = blockIdx.y, cg = blockIdx.z;
    int gj = tilec + tx;
    int r0 = tiler + ty * 4;

    for (int cc = 0; cc < 8; cc++) {
        int c = cg * 8 + cc;
        const float* xp = vid + (t * NC + c) * HW;
        float x[6][3];
#pragma unroll
        for (int rr = 0; rr < 6; rr++) {
            int yy = r0 + rr - 1;
            bool yok = (yy >= 0 && yy < NH);
#pragma unroll
            for (int jj = 0; jj < 3; jj++) {
                int xxc = gj + jj - 1;
                x[rr][jj] = (yok && xxc >= 0 && xxc < NW) ? xp[yy * NW + xxc] : 0.f;
            }
        }
        float wqr[9], wkr[9], wvr[9];
#pragma unroll
        for (int i = 0; i < 9; i++) {
            wqr[i] = wq[c * 9 + i]; wkr[i] = wk[c * 9 + i]; wvr[i] = wv[c * 9 + i];
        }
#pragma unroll
        for (int p = 0; p < 4; p++) {
            float sq = 0.f, sk = 0.f, sv = 0.f;
#pragma unroll
            for (int ky = 0; ky < 3; ky++)
#pragma unroll
                for (int kx = 0; kx < 3; kx++) {
                    float xv = x[p + ky][kx];
                    sq = fmaf(xv, wqr[ky * 3 + kx], sq);
                    sk = fmaf(xv, wkr[ky * 3 + kx], sk);
                    sv = fmaf(xv, wvr[ky * 3 + kx], sv);
                }
            int pix = (r0 + p) * NW + gj;
            g_dw[0][t][c][pix] = sq;
            g_dw[1][t][c][pix] = sk;
            g_dw[2][t][c][pix] = sv;
        }
    }
}

// ================= GEMM core (BM=128, 2 blocks/SM) — R9 best =================
__device__ __forceinline__ void gemm_core(
    const float* __restrict__ WT, const float* __restrict__ bias,
    const float* __restrict__ X, int xstride, int x0,
    float (&va)[4][16])
{
    extern __shared__ float sm[];
    float* Ws = sm;                 // [128][128]
    float* Xs = sm + NC * NC;       // [2][16][128]
    const int tid = threadIdx.x;
    const int tm = tid & 31, tn = tid >> 5;
    const int n0 = tn * 16;

#pragma unroll
    for (int i = 0; i < 16; i++)
        reinterpret_cast<float4*>(Ws)[tid + i * 256] =
            reinterpret_cast<const float4*>(WT)[tid + i * 256];

    {
        int f0 = tid * 2;
#pragma unroll
        for (int j = 0; j < 2; j++) {
            int f = f0 + j, kk = f >> 5, m4 = f & 31;
            reinterpret_cast<float4*>(Xs)[f] =
                *reinterpret_cast<const float4*>(&X[(size_t)kk * xstride + x0 + m4 * 4]);
        }
    }
    __syncthreads();

    ull acc[4][8];
#pragma unroll
    for (int c = 0; c < 8; c++) {
        ull b = pk2(bias[n0 + 2 * c], bias[n0 + 2 * c + 1]);
#pragma unroll
        for (int i = 0; i < 4; i++) acc[i][c] = b;
    }

#pragma unroll 1
    for (int kc = 0; kc < 8; kc++) {
        float4 pre[2];
        if (kc < 7) {
            int f0 = tid * 2;
#pragma unroll
            for (int j = 0; j < 2; j++) {
                int f = f0 + j, kk = (kc + 1) * 16 + (f >> 5), m4 = f & 31;
                pre[j] = *reinterpret_cast<const float4*>(&X[(size_t)kk * xstride + x0 + m4 * 4]);
            }
        }
        const float* Xb = Xs + (kc & 1) * (16 * 128);
#pragma unroll
        for (int k = 0; k < 16; k++) {
            float4 a4 = *reinterpret_cast<const float4*>(&Xb[k * 128 + tm * 4]);
            ull ad0 = pk2(a4.x, a4.x), ad1 = pk2(a4.y, a4.y);
            ull ad2 = pk2(a4.z, a4.z), ad3 = pk2(a4.w, a4.w);
            const float* Wk = Ws + (kc * 16 + k) * 128 + n0;
#pragma unroll
            for (int c4 = 0; c4 < 4; c4++) {
                ulonglong2 bp = *reinterpret_cast<const ulonglong2*>(Wk + c4 * 4);
                fma2(acc[0][2 * c4 + 0], ad0, bp.x);
                fma2(acc[0][2 * c4 + 1], ad0, bp.y);
                fma2(acc[1][2 * c4 + 0], ad1, bp.x);
                fma2(acc[1][2 * c4 + 1], ad1, bp.y);
                fma2(acc[2][2 * c4 + 0], ad2, bp.x);
                fma2(acc[2][2 * c4 + 1], ad2, bp.y);
                fma2(acc[3][2 * c4 + 0], ad3, bp.x);
                fma2(acc[3][2 * c4 + 1], ad3, bp.y);
            }
        }
        if (kc < 7) {
            float* Xn = Xs + ((kc + 1) & 1) * (16 * 128);
            int f0 = tid * 2;
#pragma unroll
            for (int j = 0; j < 2; j++)
                reinterpret_cast<float4*>(Xn)[f0 + j] = pre[j];
            __syncthreads();
        }
    }

#pragma unroll
    for (int i = 0; i < 4; i++)
#pragma unroll
        for (int c = 0; c < 8; c++) upk2(acc[i][c], va[i][2 * c], va[i][2 * c + 1]);
}

// ---------------- kernel 2: pointwise 1x1 GEMM ----------------
__global__ __launch_bounds__(256, 2) void pw_kernel(
    const float* __restrict__ bq_, const float* __restrict__ bk_,
    const float* __restrict__ bv_)
{
    int pix0 = blockIdx.x * 128;
    int t = blockIdx.y, proj = blockIdx.z;
    const float* bias = (proj == 0) ? bq_ : (proj == 1) ? bk_ : bv_;
    const float* X = &g_dw[proj][t][0][0];

    float va[4][16];
    gemm_core(&g_WT[proj][0][0], bias, X, HW, pix0, va);

    const int tm = threadIdx.x & 31, tn = threadIdx.x >> 5;
    const int n0 = tn * 16;

    if (proj == 0) {
#pragma unroll
        for (int i = 0; i < 4; i++)
#pragma unroll
            for (int c2 = 0; c2 < 16; c2++) va[i][c2] *= QSCALE;
    }

    if (proj < 2) {
        float* dst = ((proj == 0) ? g_q : g_k) + t * NC * HW;
#pragma unroll
        for (int c2 = 0; c2 < 16; c2++)
            *reinterpret_cast<float4*>(&dst[(n0 + c2) * HW + pix0 + tm * 4]) =
                make_float4(va[0][c2], va[1][c2], va[2][c2], va[3][c2]);
    } else {
        int h = n0 >> 5, dd = n0 & 31;
#pragma unroll
        for (int i = 0; i < 4; i++) {
            int pix = pix0 + tm * 4 + i;
            float* vp = &g_vT[((size_t)(t * HEADS + h) * HW + pix) * HD + dd];
#pragma unroll
            for (int j = 0; j < 4; j++)
                *reinterpret_cast<float4*>(&vp[j * 4]) =
                    make_float4(va[i][4 * j], va[i][4 * j + 1], va[i][4 * j + 2], va[i][4 * j + 3]);
        }
    }
}

// ---------------- kernel 4: final projection GEMM ----------------
__global__ __launch_bounds__(256, 2) void proj_kernel(
    const float* __restrict__ pb, float* __restrict__ out)
{
    int q0 = blockIdx.x * 128;
    int t = q0 / HW, hw0 = q0 - t * HW;

    float va[4][16];
    gemm_core(&g_WT[3][0][0], pb, g_att, NQ, q0, va);

    const int tm = threadIdx.x & 31, tn = threadIdx.x >> 5;
    const int n0 = tn * 16;
#pragma unroll
    for (int c2 = 0; c2 < 16; c2++)
        *reinterpret_cast<float4*>(&out[(size_t)(t * NC + n0 + c2) * HW + hw0 + tm * 4]) =
            make_float4(va[0][c2], va[1][c2], va[2][c2], va[3][c2]);
}

// ---------------- kernel 3: non-local attention (chunked top-k, b64 direct loads) ----------------
#define CEA(A, i, j) do { unsigned _a = A[i], _b = A[j]; \
    A[i] = (_a > _b) ? _a : _b; A[j] = (_a > _b) ? _b : _a; } while (0)

#define SORT8A(A, o) do { \
    CEA(A,o+0,o+1); CEA(A,o+2,o+3); CEA(A,o+4,o+5); CEA(A,o+6,o+7); \
    CEA(A,o+0,o+2); CEA(A,o+1,o+3); CEA(A,o+4,o+6); CEA(A,o+5,o+7); \
    CEA(A,o+1,o+2); CEA(A,o+5,o+6); \
    CEA(A,o+0,o+4); CEA(A,o+1,o+5); CEA(A,o+2,o+6); CEA(A,o+3,o+7); \
    CEA(A,o+2,o+4); CEA(A,o+3,o+5); \
    CEA(A,o+1,o+2); CEA(A,o+3,o+4); CEA(A,o+5,o+6); } while (0)

#define BM8A(A, o) do { \
    CEA(A,o+0,o+4); CEA(A,o+1,o+5); CEA(A,o+2,o+6); CEA(A,o+3,o+7); \
    CEA(A,o+0,o+2); CEA(A,o+1,o+3); CEA(A,o+4,o+6); CEA(A,o+5,o+7); \
    CEA(A,o+0,o+1); CEA(A,o+2,o+3); CEA(A,o+4,o+5); CEA(A,o+6,o+7); } while (0)

#define MERGE16A(A) do { \
    CEA(A,0,15); CEA(A,1,14); CEA(A,2,13); CEA(A,3,12); \
    CEA(A,4,11); CEA(A,5,10); CEA(A,6,9);  CEA(A,7,8); \
    BM8A(A,0); BM8A(A,8); } while (0)

#define SORTB16A(A) do { \
    CEA(A,0,8);  CEA(A,1,9);  CEA(A,2,10); CEA(A,3,11); \
    CEA(A,4,12); CEA(A,5,13); CEA(A,6,14); CEA(A,7,15); \
    BM8A(A,0); BM8A(A,8); } while (0)

__global__ __launch_bounds__(256, 2) void attn_kernel()
{
    extern __shared__ float sm[];
    const int tid = threadIdx.x;
    const int tx = tid & 31, ty = tid >> 5;
    const int tcx = (blockIdx.x % 3) * TW, trow = (blockIdx.x / 3) * TH;
    const int h = blockIdx.y, t = blockIdx.z;
    const int base = (t * NC + h * HD) * HW;
    const int br = trow - 4, bc = tcx - 4;

    // stage reflected k halo, d-quads interleaved: float4 [d4][lp]
    for (int idx = tid; idx < 8 * HP; idx += 256) {
        int d4 = idx / HP, lp = idx - d4 * HP;
        int lr = lp / HC, lc = lp - lr * HC;
        int ri = refl(br + lr), rj = refl(bc + lc);
        const float* gp = g_k + base + (d4 * 4) * HW + ri * NW + rj;
        reinterpret_cast<float4*>(sm)[idx] =
            make_float4(gp[0], gp[HW], gp[2 * HW], gp[3 * HW]);
    }
    __syncthreads();

    const int gi = trow + ty, gj = tcx + tx;
    const int pix = gi * NW + gj;

    ull q2[16];
#pragma unroll
    for (int d2 = 0; d2 < 16; d2++)
        q2[d2] = pk2(g_q[base + (2 * d2) * HW + pix], g_q[base + (2 * d2 + 1) * HW + pix]);

    unsigned top[16];
    unsigned mxkey = 0;

#pragma unroll
    for (int ch = 0; ch < 4; ch++) {
        unsigned key[16];
#pragma unroll
        for (int a2 = 0; a2 < 2; a2++) {
            int arow = 2 * ch + a2;
#pragma unroll
            for (int b = 0; b < 8; b++) {
                int lp = (ty + arow) * HC + (tx + b);
                const ulonglong2* kp = reinterpret_cast<const ulonglong2*>(sm) + lp;
                ull s0 = 0ull, s1 = 0ull;
#pragma unroll
                for (int d4 = 0; d4 < 8; d4++) {
                    ulonglong2 kv = kp[d4 * HP];      // direct b64 pair, no pack movs
                    fma2(s0, q2[2 * d4],     kv.x);
                    fma2(s1, q2[2 * d4 + 1], kv.y);
                }
                float x0, x1, y0, y1;
                upk2(s0, x0, x1); upk2(s1, y0, y1);
                float s = (x0 + y0) + (x1 + y1);
                unsigned u = __float_as_uint(s);
                unsigned kk = (u & 0x80000000u) ? ~u : (u | 0x80000000u);
                key[a2 * 8 + b] = (kk & 0xFFFFFFC0u) | (unsigned)(arow * 8 + b);
            }
        }
        SORT8A(key, 0); SORT8A(key, 8);
        MERGE16A(key);
        if (ch == 0) {
            mxkey = key[0];
#pragma unroll
            for (int i = 0; i < 16; i++) top[i] = key[i];
        } else {
            if (key[0] > mxkey) mxkey = key[0];
#pragma unroll
            for (int i = 0; i < 16; i++) {
                unsigned b2 = key[15 - i];
                if (b2 > top[i]) top[i] = b2;
            }
            if (ch < 3) SORTB16A(top);
        }
    }
    __syncthreads();   // all k reads complete before overwrite

    // stage reflected v halo, pixel-major, XOR slot swizzle: float4 [lp][d4^(lp&7)]
    const float* vbase = g_vT + (size_t)(t * HEADS + h) * HW * HD;
    for (int idx = tid; idx < 8 * HP; idx += 256) {
        int lp = idx >> 3, d4 = idx & 7;
        int lr = lp / HC, lc = lp - lr * HC;
        int ri = refl(br + lr), rj = refl(bc + lc);
        float4 vv = *reinterpret_cast<const float4*>(&vbase[(size_t)(ri * NW + rj) * HD + d4 * 4]);
        reinterpret_cast<float4*>(sm)[lp * 8 + (d4 ^ (lp & 7))] = vv;
    }
    __syncthreads();

    unsigned mu = (mxkey & 0x80000000u) ? (mxkey ^ 0x80000000u) : ~mxkey;
    float mxv = __uint_as_float(mu);

    float wgt[16]; int lps[16];
    float wsum = 0.f;
#pragma unroll
    for (int p = 0; p < 16; p++) {
        unsigned kk = top[p];
        int ci = kk & 63;
        unsigned u = (kk & 0x80000000u) ? (kk ^ 0x80000000u) : ~kk;
        float e = __expf(__uint_as_float(u) - mxv);
        wsum += e;
        wgt[p] = e;
        lps[p] = (ty + (ci >> 3)) * HC + (tx + (ci & 7));
    }

    ull acc2[16];
#pragma unroll
    for (int c = 0; c < 16; c++) acc2[c] = 0ull;
#pragma unroll
    for (int p = 0; p < 16; p++) {
        int lp = lps[p];
        const ulonglong2* vp = reinterpret_cast<const ulonglong2*>(sm) + lp * 8;  // 16B units, pixel row = 8 units
        int sw = lp & 7;
        ull e2 = pk2(wgt[p], wgt[p]);
#pragma unroll
        for (int d4 = 0; d4 < 8; d4++) {
            ulonglong2 vv = vp[d4 ^ sw];              // direct b64 pair, no pack movs
            fma2(acc2[2 * d4],     e2, vv.x);
            fma2(acc2[2 * d4 + 1], e2, vv.y);
        }
    }

    float inv = 1.f / wsum;
    const int qg = t * HW + pix;
#pragma unroll
    for (int c = 0; c < 16; c++) {
        float lo, hi;
        upk2(acc2[c], lo, hi);
        g_att[(size_t)(h * HD + 2 * c) * NQ + qg] = lo * inv;
        g_att[(size_t)(h * HD + 2 * c + 1) * NQ + qg] = hi * inv;
    }
}

// ---------------- launch ----------------
extern "C" void kernel_launch(void* const* d_in, const int* in_sizes, int n_in,
                              void* d_out, int out_size)
{
    const float* vid    = (const float*)d_in[0];
    const float* wq_dw  = (const float*)d_in[1];
    const float* wq_pw  = (const float*)d_in[2];
    const float* bq     = (const float*)d_in[3];
    const float* wk_dw  = (const float*)d_in[4];
    const float* wk_pw  = (const float*)d_in[5];
    const float* bk     = (const float*)d_in[6];
    const float* wv_dw  = (const float*)d_in[7];
    const float* wv_pw  = (const float*)d_in[8];
    const float* bv     = (const float*)d_in[9];
    const float* proj_w = (const float*)d_in[10];
    const float* proj_b = (const float*)d_in[11];
    float* out = (float*)d_out;

    const int attn_smem = 8 * HP * 16;                        // 74880
    const int gemm_smem = (NC * NC + 2 * 16 * NC) * (int)sizeof(float);  // 81920
    cudaFuncSetAttribute(attn_kernel, cudaFuncAttributeMaxDynamicSharedMemorySize, attn_smem);
    cudaFuncSetAttribute(pw_kernel, cudaFuncAttributeMaxDynamicSharedMemorySize, gemm_smem);
    cudaFuncSetAttribute(proj_kernel, cudaFuncAttributeMaxDynamicSharedMemorySize, gemm_smem);

    wt_kernel<<<dim3(16, 4), 256>>>(wq_pw, wk_pw, wv_pw, proj_w);
    dw_kernel<<<dim3(9, 2, 16), 256>>>(vid, wq_dw, wk_dw, wv_dw);
    pw_kernel<<<dim3(72, 2, 3), 256, gemm_smem>>>(bq, bk, bv);
    attn_kernel<<<dim3(36, 4, 2), 256, attn_smem>>>();
    proj_kernel<<<dim3(144, 1, 1), 256, gemm_smem>>>(proj_b, out);
}

// round 16
// speedup vs baseline: 1.5814x; 1.0198x over previous
#include <cuda_runtime.h>
#include <cstdint>

#define NT 2
#define NC 128
#define NH 96
#define NW 96
#define HW 9216        // 96*96
#define NQ 18432       // NT*HW
#define HEADS 4
#define HD 32
#define QSCALE 0.17677669529663687f

// attention tile: 32 wide x 8 high
#define TW 32
#define TH 8
#define HC 39          // TW + 7
#define HR 15          // TH + 7
#define HP 585         // HR*HC

typedef unsigned long long ull;

// ---------------- scratch ----------------
__device__ __align__(16) float g_dw[3][NT][NC][HW];          // depthwise results q/k/v
__device__ __align__(16) float g_q[NT * NC * HW];            // [t*128+c][pix]
__device__ __align__(16) float g_k[NT * NC * HW];            // [t*128+c][pix]
__device__ __align__(16) float g_vT[NT * HEADS * HW * HD];   // [t][h][pix][d]
__device__ __align__(16) float g_att[NC * NQ];               // [c][q]  channel-major
__device__ __align__(16) float g_WT[4][NC][NC];              // transposed weights [k][n]

// ---------------- f32x2 helpers ----------------
__device__ __forceinline__ ull pk2(float lo, float hi) {
    ull r;
    asm("mov.b64 %0, {%1, %2};" : "=l"(r) : "f"(lo), "f"(hi));
    return r;
}
__device__ __forceinline__ void upk2(ull v, float& lo, float& hi) {
    asm("mov.b64 {%0, %1}, %2;" : "=f"(lo), "=f"(hi) : "l"(v));
}
__device__ __forceinline__ void fma2(ull& d, ull a, ull b) {
    asm("fma.rn.f32x2 %0, %1, %2, %0;" : "+l"(d) : "l"(a), "l"(b));
}
__device__ __forceinline__ int refl(int i) {
    i = (i < 0) ? -i : i;
    return (i > 95) ? 190 - i : i;
}

// ---------------- kernel 0: transpose weights into [k][n] ----------------
__global__ __launch_bounds__(256) void wt_kernel(
    const float* __restrict__ w0, const float* __restrict__ w1,
    const float* __restrict__ w2, const float* __restrict__ w3)
{
    __shared__ float tile[32][33];
    const float* srcs[4] = {w0, w1, w2, w3};
    int m = blockIdx.y;
    const float* W = srcs[m];
    int tr = blockIdx.x >> 2, tc = blockIdx.x & 3;   // 4x4 tiles of 32x32
    int tx = threadIdx.x & 31, ty = threadIdx.x >> 5;
#pragma unroll
    for (int i = 0; i < 4; i++)
        tile[ty * 4 + i][tx] = W[(tr * 32 + ty * 4 + i) * NC + tc * 32 + tx];
    __syncthreads();
#pragma unroll
    for (int i = 0; i < 4; i++)
        g_WT[m][tc * 32 + ty * 4 + i][tr * 32 + tx] = tile[tx][ty * 4 + i];
}

// ---------------- kernel 1: depthwise 3x3, zero-pad SAME ----------------
__global__ __launch_bounds__(256) void dw_kernel(
    const float* __restrict__ vid,
    const float* __restrict__ wq, const float* __restrict__ wk,
    const float* __restrict__ wv)
{
    int tid = threadIdx.x;
    int tx = tid & 31, ty = tid >> 5;
    int tilec = (blockIdx.x % 3) * 32, tiler = (blockIdx.x / 3) * 32;
    int t = blockIdx.y, cg = blockIdx.z;
    int gj = tilec + tx;
    int r0 = tiler + ty * 4;

    for (int cc = 0; cc < 8; cc++) {
        int c = cg * 8 + cc;
        const float* xp = vid + (t * NC + c) * HW;
        float x[6][3];
#pragma unroll
        for (int rr = 0; rr < 6; rr++) {
            int yy = r0 + rr - 1;
            bool yok = (yy >= 0 && yy < NH);
#pragma unroll
            for (int jj = 0; jj < 3; jj++) {
                int xxc = gj + jj - 1;
                x[rr][jj] = (yok && xxc >= 0 && xxc < NW) ? xp[yy * NW + xxc] : 0.f;
            }
        }
        float wqr[9], wkr[9], wvr[9];
#pragma unroll
        for (int i = 0; i < 9; i++) {
            wqr[i] = wq[c * 9 + i]; wkr[i] = wk[c * 9 + i]; wvr[i] = wv[c * 9 + i];
        }
#pragma unroll
        for (int p = 0; p < 4; p++) {
            float sq = 0.f, sk = 0.f, sv = 0.f;
#pragma unroll
            for (int ky = 0; ky < 3; ky++)
#pragma unroll
                for (int kx = 0; kx < 3; kx++) {
                    float xv = x[p + ky][kx];
                    sq = fmaf(xv, wqr[ky * 3 + kx], sq);
                    sk = fmaf(xv, wkr[ky * 3 + kx], sk);
                    sv = fmaf(xv, wvr[ky * 3 + kx], sv);
                }
            int pix = (r0 + p) * NW + gj;
            g_dw[0][t][c][pix] = sq;
            g_dw[1][t][c][pix] = sk;
            g_dw[2][t][c][pix] = sv;
        }
    }
}

// ================= GEMM core (BM=128, 2 blocks/SM) =================
__device__ __forceinline__ void gemm_core(
    const float* __restrict__ WT, const float* __restrict__ bias,
    const float* __restrict__ X, int xstride, int x0,
    float (&va)[4][16])
{
    extern __shared__ float sm[];
    float* Ws = sm;                 // [128][128]
    float* Xs = sm + NC * NC;       // [2][16][128]
    const int tid = threadIdx.x;
    const int tm = tid & 31, tn = tid >> 5;
    const int n0 = tn * 16;

#pragma unroll
    for (int i = 0; i < 16; i++)
        reinterpret_cast<float4*>(Ws)[tid + i * 256] =
            reinterpret_cast<const float4*>(WT)[tid + i * 256];

    {
        int f0 = tid * 2;
#pragma unroll
        for (int j = 0; j < 2; j++) {
            int f = f0 + j, kk = f >> 5, m4 = f & 31;
            reinterpret_cast<float4*>(Xs)[f] =
                *reinterpret_cast<const float4*>(&X[(size_t)kk * xstride + x0 + m4 * 4]);
        }
    }
    __syncthreads();

    ull acc[4][8];
#pragma unroll
    for (int c = 0; c < 8; c++) {
        ull b = pk2(bias[n0 + 2 * c], bias[n0 + 2 * c + 1]);
#pragma unroll
        for (int i = 0; i < 4; i++) acc[i][c] = b;
    }

#pragma unroll 1
    for (int kc = 0; kc < 8; kc++) {
        float4 pre[2];
        if (kc < 7) {
            int f0 = tid * 2;
#pragma unroll
            for (int j = 0; j < 2; j++) {
                int f = f0 + j, kk = (kc + 1) * 16 + (f >> 5), m4 = f & 31;
                pre[j] = *reinterpret_cast<const float4*>(&X[(size_t)kk * xstride + x0 + m4 * 4]);
            }
        }
        const float* Xb = Xs + (kc & 1) * (16 * 128);
#pragma unroll
        for (int k = 0; k < 16; k++) {
            float4 a4 = *reinterpret_cast<const float4*>(&Xb[k * 128 + tm * 4]);
            ull ad0 = pk2(a4.x, a4.x), ad1 = pk2(a4.y, a4.y);
            ull ad2 = pk2(a4.z, a4.z), ad3 = pk2(a4.w, a4.w);
            const float* Wk = Ws + (kc * 16 + k) * 128 + n0;
#pragma unroll
            for (int c4 = 0; c4 < 4; c4++) {
                ulonglong2 bp = *reinterpret_cast<const ulonglong2*>(Wk + c4 * 4);
                fma2(acc[0][2 * c4 + 0], ad0, bp.x);
                fma2(acc[0][2 * c4 + 1], ad0, bp.y);
                fma2(acc[1][2 * c4 + 0], ad1, bp.x);
                fma2(acc[1][2 * c4 + 1], ad1, bp.y);
                fma2(acc[2][2 * c4 + 0], ad2, bp.x);
                fma2(acc[2][2 * c4 + 1], ad2, bp.y);
                fma2(acc[3][2 * c4 + 0], ad3, bp.x);
                fma2(acc[3][2 * c4 + 1], ad3, bp.y);
            }
        }
        if (kc < 7) {
            float* Xn = Xs + ((kc + 1) & 1) * (16 * 128);
            int f0 = tid * 2;
#pragma unroll
            for (int j = 0; j < 2; j++)
                reinterpret_cast<float4*>(Xn)[f0 + j] = pre[j];
            __syncthreads();
        }
    }

#pragma unroll
    for (int i = 0; i < 4; i++)
#pragma unroll
        for (int c = 0; c < 8; c++) upk2(acc[i][c], va[i][2 * c], va[i][2 * c + 1]);
}

// ---------------- kernel 2: pointwise 1x1 GEMM ----------------
__global__ __launch_bounds__(256, 2) void pw_kernel(
    const float* __restrict__ bq_, const float* __restrict__ bk_,
    const float* __restrict__ bv_)
{
    int pix0 = blockIdx.x * 128;
    int t = blockIdx.y, proj = blockIdx.z;
    const float* bias = (proj == 0) ? bq_ : (proj == 1) ? bk_ : bv_;
    const float* X = &g_dw[proj][t][0][0];

    float va[4][16];
    gemm_core(&g_WT[proj][0][0], bias, X, HW, pix0, va);

    const int tm = threadIdx.x & 31, tn = threadIdx.x >> 5;
    const int n0 = tn * 16;

    if (proj == 0) {
#pragma unroll
        for (int i = 0; i < 4; i++)
#pragma unroll
            for (int c2 = 0; c2 < 16; c2++) va[i][c2] *= QSCALE;
    }

    if (proj < 2) {
        float* dst = ((proj == 0) ? g_q : g_k) + t * NC * HW;
#pragma unroll
        for (int c2 = 0; c2 < 16; c2++)
            *reinterpret_cast<float4*>(&dst[(n0 + c2) * HW + pix0 + tm * 4]) =
                make_float4(va[0][c2], va[1][c2], va[2][c2], va[3][c2]);
    } else {
        int h = n0 >> 5, dd = n0 & 31;
#pragma unroll
        for (int i = 0; i < 4; i++) {
            int pix = pix0 + tm * 4 + i;
            float* vp = &g_vT[((size_t)(t * HEADS + h) * HW + pix) * HD + dd];
#pragma unroll
            for (int j = 0; j < 4; j++)
                *reinterpret_cast<float4*>(&vp[j * 4]) =
                    make_float4(va[i][4 * j], va[i][4 * j + 1], va[i][4 * j + 2], va[i][4 * j + 3]);
        }
    }
}

// ---------------- kernel 4: final projection GEMM ----------------
__global__ __launch_bounds__(256, 2) void proj_kernel(
    const float* __restrict__ pb, float* __restrict__ out)
{
    int q0 = blockIdx.x * 128;
    int t = q0 / HW, hw0 = q0 - t * HW;

    float va[4][16];
    gemm_core(&g_WT[3][0][0], pb, g_att, NQ, q0, va);

    const int tm = threadIdx.x & 31, tn = threadIdx.x >> 5;
    const int n0 = tn * 16;
#pragma unroll
    for (int c2 = 0; c2 < 16; c2++)
        *reinterpret_cast<float4*>(&out[(size_t)(t * NC + n0 + c2) * HW + hw0 + tm * 4]) =
            make_float4(va[0][c2], va[1][c2], va[2][c2], va[3][c2]);
}

// ---------------- kernel 3: non-local attention (chunked top-k, b64 direct loads) ----------------
#define CEA(A, i, j) do { unsigned _a = A[i], _b = A[j]; \
    A[i] = (_a > _b) ? _a : _b; A[j] = (_a > _b) ? _b : _a; } while (0)

#define SORT8A(A, o) do { \
    CEA(A,o+0,o+1); CEA(A,o+2,o+3); CEA(A,o+4,o+5); CEA(A,o+6,o+7); \
    CEA(A,o+0,o+2); CEA(A,o+1,o+3); CEA(A,o+4,o+6); CEA(A,o+5,o+7); \
    CEA(A,o+1,o+2); CEA(A,o+5,o+6); \
    CEA(A,o+0,o+4); CEA(A,o+1,o+5); CEA(A,o+2,o+6); CEA(A,o+3,o+7); \
    CEA(A,o+2,o+4); CEA(A,o+3,o+5); \
    CEA(A,o+1,o+2); CEA(A,o+3,o+4); CEA(A,o+5,o+6); } while (0)

#define BM8A(A, o) do { \
    CEA(A,o+0,o+4); CEA(A,o+1,o+5); CEA(A,o+2,o+6); CEA(A,o+3,o+7); \
    CEA(A,o+0,o+2); CEA(A,o+1,o+3); CEA(A,o+4,o+6); CEA(A,o+5,o+7); \
    CEA(A,o+0,o+1); CEA(A,o+2,o+3); CEA(A,o+4,o+5); CEA(A,o+6,o+7); } while (0)

#define MERGE16A(A) do { \
    CEA(A,0,15); CEA(A,1,14); CEA(A,2,13); CEA(A,3,12); \
    CEA(A,4,11); CEA(A,5,10); CEA(A,6,9);  CEA(A,7,8); \
    BM8A(A,0); BM8A(A,8); } while (0)

#define SORTB16A(A) do { \
    CEA(A,0,8);  CEA(A,1,9);  CEA(A,2,10); CEA(A,3,11); \
    CEA(A,4,12); CEA(A,5,13); CEA(A,6,14); CEA(A,7,15); \
    BM8A(A,0); BM8A(A,8); } while (0)

__global__ __launch_bounds__(256, 2) void attn_kernel()
{
    extern __shared__ float sm[];
    const int tid = threadIdx.x;
    const int tx = tid & 31, ty = tid >> 5;
    const int tcx = (blockIdx.x % 3) * TW, trow = (blockIdx.x / 3) * TH;
    const int h = blockIdx.y, t = blockIdx.z;
    const int base = (t * NC + h * HD) * HW;
    const int br = trow - 4, bc = tcx - 4;

    // stage reflected k halo, d-quads interleaved: float4 [d4][lp]
    for (int idx = tid; idx < 8 * HP; idx += 256) {
        int d4 = idx / HP, lp = idx - d4 * HP;
        int lr = lp / HC, lc = lp - lr * HC;
        int ri = refl(br + lr), rj = refl(bc + lc);
        const float* gp = g_k + base + (d4 * 4) * HW + ri * NW + rj;
        reinterpret_cast<float4*>(sm)[idx] =
            make_float4(gp[0], gp[HW], gp[2 * HW], gp[3 * HW]);
    }
    __syncthreads();

    const int gi = trow + ty, gj = tcx + tx;
    const int pix = gi * NW + gj;

    ull q2[16];
#pragma unroll
    for (int d2 = 0; d2 < 16; d2++)
        q2[d2] = pk2(g_q[base + (2 * d2) * HW + pix], g_q[base + (2 * d2 + 1) * HW + pix]);

    unsigned top[16];
    unsigned mxkey = 0;

#pragma unroll
    for (int ch = 0; ch < 4; ch++) {
        unsigned key[16];
#pragma unroll
        for (int a2 = 0; a2 < 2; a2++) {
            int arow = 2 * ch + a2;
#pragma unroll
            for (int b = 0; b < 8; b++) {
                int lp = (ty + arow) * HC + (tx + b);
                const ulonglong2* kp = reinterpret_cast<const ulonglong2*>(sm) + lp;
                ull s0 = 0ull, s1 = 0ull;
#pragma unroll
                for (int d4 = 0; d4 < 8; d4++) {
                    ulonglong2 kv = kp[d4 * HP];      // direct b64 pair, no pack movs
                    fma2(s0, q2[2 * d4],     kv.x);
                    fma2(s1, q2[2 * d4 + 1], kv.y);
                }
                float x0, x1, y0, y1;
                upk2(s0, x0, x1); upk2(s1, y0, y1);
                float s = (x0 + y0) + (x1 + y1);
                unsigned u = __float_as_uint(s);
                unsigned kk = (u & 0x80000000u) ? ~u : (u | 0x80000000u);
                key[a2 * 8 + b] = (kk & 0xFFFFFFC0u) | (unsigned)(arow * 8 + b);
            }
        }
        SORT8A(key, 0); SORT8A(key, 8);
        MERGE16A(key);
        if (ch == 0) {
            mxkey = key[0];
#pragma unroll
            for (int i = 0; i < 16; i++) top[i] = key[i];
        } else {
            if (key[0] > mxkey) mxkey = key[0];
#pragma unroll
            for (int i = 0; i < 16; i++) {
                unsigned b2 = key[15 - i];
                if (b2 > top[i]) top[i] = b2;
            }
            if (ch < 3) SORTB16A(top);
        }
    }
    __syncthreads();   // all k reads complete before overwrite

    // stage reflected v halo, pixel-major, XOR slot swizzle: float4 [lp][d4^(lp&7)]
    const float* vbase = g_vT + (size_t)(t * HEADS + h) * HW * HD;
    for (int idx = tid; idx < 8 * HP; idx += 256) {
        int lp = idx >> 3, d4 = idx & 7;
        int lr = lp / HC, lc = lp - lr * HC;
        int ri = refl(br + lr), rj = refl(bc + lc);
        float4 vv = *reinterpret_cast<const float4*>(&vbase[(size_t)(ri * NW + rj) * HD + d4 * 4]);
        reinterpret_cast<float4*>(sm)[lp * 8 + (d4 ^ (lp & 7))] = vv;
    }
    __syncthreads();

    unsigned mu = (mxkey & 0x80000000u) ? (mxkey ^ 0x80000000u) : ~mxkey;
    float mxv = __uint_as_float(mu);

    float wgt[16]; int lps[16];
    float wsum = 0.f;
#pragma unroll
    for (int p = 0; p < 16; p++) {
        unsigned kk = top[p];
        int ci = kk & 63;
        unsigned u = (kk & 0x80000000u) ? (kk ^ 0x80000000u) : ~kk;
        float e = __expf(__uint_as_float(u) - mxv);
        wsum += e;
        wgt[p] = e;
        lps[p] = (ty + (ci >> 3)) * HC + (tx + (ci & 7));
    }

    ull acc2[16];
#pragma unroll
    for (int c = 0; c < 16; c++) acc2[c] = 0ull;
#pragma unroll
    for (int p = 0; p < 16; p++) {
        int lp = lps[p];
        const ulonglong2* vp = reinterpret_cast<const ulonglong2*>(sm) + lp * 8;  // 16B units, pixel row = 8 units
        int sw = lp & 7;
        ull e2 = pk2(wgt[p], wgt[p]);
#pragma unroll
        for (int d4 = 0; d4 < 8; d4++) {
            ulonglong2 vv = vp[d4 ^ sw];              // direct b64 pair, no pack movs
            fma2(acc2[2 * d4],     e2, vv.x);
            fma2(acc2[2 * d4 + 1], e2, vv.y);
        }
    }

    float inv = 1.f / wsum;
    const int qg = t * HW + pix;
#pragma unroll
    for (int c = 0; c < 16; c++) {
        float lo, hi;
        upk2(acc2[c], lo, hi);
        g_att[(size_t)(h * HD + 2 * c) * NQ + qg] = lo * inv;
        g_att[(size_t)(h * HD + 2 * c + 1) * NQ + qg] = hi * inv;
    }
}

// ---------------- launch ----------------
extern "C" void kernel_launch(void* const* d_in, const int* in_sizes, int n_in,
                              void* d_out, int out_size)
{
    const float* vid    = (const float*)d_in[0];
    const float* wq_dw  = (const float*)d_in[1];
    const float* wq_pw  = (const float*)d_in[2];
    const float* bq     = (const float*)d_in[3];
    const float* wk_dw  = (const float*)d_in[4];
    const float* wk_pw  = (const float*)d_in[5];
    const float* bk     = (const float*)d_in[6];
    const float* wv_dw  = (const float*)d_in[7];
    const float* wv_pw  = (const float*)d_in[8];
    const float* bv     = (const float*)d_in[9];
    const float* proj_w = (const float*)d_in[10];
    const float* proj_b = (const float*)d_in[11];
    float* out = (float*)d_out;

    const int attn_smem = 8 * HP * 16;                        // 74880
    const int gemm_smem = (NC * NC + 2 * 16 * NC) * (int)sizeof(float);  // 81920
    cudaFuncSetAttribute(attn_kernel, cudaFuncAttributeMaxDynamicSharedMemorySize, attn_smem);
    cudaFuncSetAttribute(pw_kernel, cudaFuncAttributeMaxDynamicSharedMemorySize, gemm_smem);
    cudaFuncSetAttribute(proj_kernel, cudaFuncAttributeMaxDynamicSharedMemorySize, gemm_smem);

    wt_kernel<<<dim3(16, 4), 256>>>(wq_pw, wk_pw, wv_pw, proj_w);
    dw_kernel<<<dim3(9, 2, 16), 256>>>(vid, wq_dw, wk_dw, wv_dw);
    pw_kernel<<<dim3(72, 2, 3), 256, gemm_smem>>>(bq, bk, bv);
    attn_kernel<<<dim3(36, 4, 2), 256, attn_smem>>>();
    proj_kernel<<<dim3(144, 1, 1), 256, gemm_smem>>>(proj_b, out);
}

// round 17
// speedup vs baseline: 1.5819x; 1.0003x over previous
#include <cuda_runtime.h>
#include <cstdint>

#define NT 2
#define NC 128
#define NH 96
#define NW 96
#define HW 9216        // 96*96
#define NQ 18432       // NT*HW
#define HEADS 4
#define HD 32
#define QSCALE 0.17677669529663687f

// attention tile: 32 wide x 8 high
#define TW 32
#define TH 8
#define HC 39          // TW + 7
#define HR 15          // TH + 7
#define HP 585         // HR*HC

typedef unsigned long long ull;

// ---------------- scratch ----------------
__device__ __align__(16) float g_dw[3][NT][NC][HW];          // depthwise results q/k/v
__device__ __align__(16) float g_q[NT * NC * HW];            // [t*128+c][pix]
__device__ __align__(16) float g_k[NT * NC * HW];            // [t*128+c][pix]
__device__ __align__(16) float g_vT[NT * HEADS * HW * HD];   // [t][h][pix][d]
__device__ __align__(16) float g_att[NC * NQ];               // [c][q]  channel-major
__device__ __align__(16) float g_WT[4][NC][NC];              // transposed weights [k][n]

// ---------------- f32x2 helpers ----------------
__device__ __forceinline__ ull pk2(float lo, float hi) {
    ull r;
    asm("mov.b64 %0, {%1, %2};" : "=l"(r) : "f"(lo), "f"(hi));
    return r;
}
__device__ __forceinline__ void upk2(ull v, float& lo, float& hi) {
    asm("mov.b64 {%0, %1}, %2;" : "=f"(lo), "=f"(hi) : "l"(v));
}
__device__ __forceinline__ void fma2(ull& d, ull a, ull b) {
    asm("fma.rn.f32x2 %0, %1, %2, %0;" : "+l"(d) : "l"(a), "l"(b));
}
__device__ __forceinline__ int refl(int i) {
    i = (i < 0) ? -i : i;
    return (i > 95) ? 190 - i : i;
}

// ---------------- kernel 0: transpose weights into [k][n] ----------------
__global__ __launch_bounds__(256) void wt_kernel(
    const float* __restrict__ w0, const float* __restrict__ w1,
    const float* __restrict__ w2, const float* __restrict__ w3)
{
    __shared__ float tile[32][33];
    const float* srcs[4] = {w0, w1, w2, w3};
    int m = blockIdx.y;
    const float* W = srcs[m];
    int tr = blockIdx.x >> 2, tc = blockIdx.x & 3;   // 4x4 tiles of 32x32
    int tx = threadIdx.x & 31, ty = threadIdx.x >> 5;
#pragma unroll
    for (int i = 0; i < 4; i++)
        tile[ty * 4 + i][tx] = W[(tr * 32 + ty * 4 + i) * NC + tc * 32 + tx];
    __syncthreads();
#pragma unroll
    for (int i = 0; i < 4; i++)
        g_WT[m][tc * 32 + ty * 4 + i][tr * 32 + tx] = tile[tx][ty * 4 + i];
}

// ---------------- kernel 1: depthwise 3x3, zero-pad SAME ----------------
__global__ __launch_bounds__(256) void dw_kernel(
    const float* __restrict__ vid,
    const float* __restrict__ wq, const float* __restrict__ wk,
    const float* __restrict__ wv)
{
    int tid = threadIdx.x;
    int tx = tid & 31, ty = tid >> 5;
    int tilec = (blockIdx.x % 3) * 32, tiler = (blockIdx.x / 3) * 32;
    int t = blockIdx.y, cg = blockIdx.z;
    int gj = tilec + tx;
    int r0 = tiler + ty * 4;

    for (int cc = 0; cc < 8; cc++) {
        int c = cg * 8 + cc;
        const float* xp = vid + (t * NC + c) * HW;
        float x[6][3];
#pragma unroll
        for (int rr = 0; rr < 6; rr++) {
            int yy = r0 + rr - 1;
            bool yok = (yy >= 0 && yy < NH);
#pragma unroll
            for (int jj = 0; jj < 3; jj++) {
                int xxc = gj + jj - 1;
                x[rr][jj] = (yok && xxc >= 0 && xxc < NW) ? xp[yy * NW + xxc] : 0.f;
            }
        }
        float wqr[9], wkr[9], wvr[9];
#pragma unroll
        for (int i = 0; i < 9; i++) {
            wqr[i] = wq[c * 9 + i]; wkr[i] = wk[c * 9 + i]; wvr[i] = wv[c * 9 + i];
        }
#pragma unroll
        for (int p = 0; p < 4; p++) {
            float sq = 0.f, sk = 0.f, sv = 0.f;
#pragma unroll
            for (int ky = 0; ky < 3; ky++)
#pragma unroll
                for (int kx = 0; kx < 3; kx++) {
                    float xv = x[p + ky][kx];
                    sq = fmaf(xv, wqr[ky * 3 + kx], sq);
                    sk = fmaf(xv, wkr[ky * 3 + kx], sk);
                    sv = fmaf(xv, wvr[ky * 3 + kx], sv);
                }
            int pix = (r0 + p) * NW + gj;
            g_dw[0][t][c][pix] = sq;
            g_dw[1][t][c][pix] = sk;
            g_dw[2][t][c][pix] = sv;
        }
    }
}

// ================= GEMM core (BM=128, 2 blocks/SM) =================
__device__ __forceinline__ void gemm_core(
    const float* __restrict__ WT, const float* __restrict__ bias,
    const float* __restrict__ X, int xstride, int x0,
    float (&va)[4][16])
{
    extern __shared__ float sm[];
    float* Ws = sm;                 // [128][128]
    float* Xs = sm + NC * NC;       // [2][16][128]
    const int tid = threadIdx.x;
    const int tm = tid & 31, tn = tid >> 5;
    const int n0 = tn * 16;

#pragma unroll
    for (int i = 0; i < 16; i++)
        reinterpret_cast<float4*>(Ws)[tid + i * 256] =
            reinterpret_cast<const float4*>(WT)[tid + i * 256];

    {
        int f0 = tid * 2;
#pragma unroll
        for (int j = 0; j < 2; j++) {
            int f = f0 + j, kk = f >> 5, m4 = f & 31;
            reinterpret_cast<float4*>(Xs)[f] =
                *reinterpret_cast<const float4*>(&X[(size_t)kk * xstride + x0 + m4 * 4]);
        }
    }
    __syncthreads();

    ull acc[4][8];
#pragma unroll
    for (int c = 0; c < 8; c++) {
        ull b = pk2(bias[n0 + 2 * c], bias[n0 + 2 * c + 1]);
#pragma unroll
        for (int i = 0; i < 4; i++) acc[i][c] = b;
    }

#pragma unroll 1
    for (int kc = 0; kc < 8; kc++) {
        float4 pre[2];
        if (kc < 7) {
            int f0 = tid * 2;
#pragma unroll
            for (int j = 0; j < 2; j++) {
                int f = f0 + j, kk = (kc + 1) * 16 + (f >> 5), m4 = f & 31;
                pre[j] = *reinterpret_cast<const float4*>(&X[(size_t)kk * xstride + x0 + m4 * 4]);
            }
        }
        const float* Xb = Xs + (kc & 1) * (16 * 128);
#pragma unroll
        for (int k = 0; k < 16; k++) {
            float4 a4 = *reinterpret_cast<const float4*>(&Xb[k * 128 + tm * 4]);
            ull ad0 = pk2(a4.x, a4.x), ad1 = pk2(a4.y, a4.y);
            ull ad2 = pk2(a4.z, a4.z), ad3 = pk2(a4.w, a4.w);
            const float* Wk = Ws + (kc * 16 + k) * 128 + n0;
#pragma unroll
            for (int c4 = 0; c4 < 4; c4++) {
                ulonglong2 bp = *reinterpret_cast<const ulonglong2*>(Wk + c4 * 4);
                fma2(acc[0][2 * c4 + 0], ad0, bp.x);
                fma2(acc[0][2 * c4 + 1], ad0, bp.y);
                fma2(acc[1][2 * c4 + 0], ad1, bp.x);
                fma2(acc[1][2 * c4 + 1], ad1, bp.y);
                fma2(acc[2][2 * c4 + 0], ad2, bp.x);
                fma2(acc[2][2 * c4 + 1], ad2, bp.y);
                fma2(acc[3][2 * c4 + 0], ad3, bp.x);
                fma2(acc[3][2 * c4 + 1], ad3, bp.y);
            }
        }
        if (kc < 7) {
            float* Xn = Xs + ((kc + 1) & 1) * (16 * 128);
            int f0 = tid * 2;
#pragma unroll
            for (int j = 0; j < 2; j++)
                reinterpret_cast<float4*>(Xn)[f0 + j] = pre[j];
            __syncthreads();
        }
    }

#pragma unroll
    for (int i = 0; i < 4; i++)
#pragma unroll
        for (int c = 0; c < 8; c++) upk2(acc[i][c], va[i][2 * c], va[i][2 * c + 1]);
}

// ---------------- kernel 2: pointwise 1x1 GEMM ----------------
__global__ __launch_bounds__(256, 2) void pw_kernel(
    const float* __restrict__ bq_, const float* __restrict__ bk_,
    const float* __restrict__ bv_)
{
    int pix0 = blockIdx.x * 128;
    int t = blockIdx.y, proj = blockIdx.z;
    const float* bias = (proj == 0) ? bq_ : (proj == 1) ? bk_ : bv_;
    const float* X = &g_dw[proj][t][0][0];

    float va[4][16];
    gemm_core(&g_WT[proj][0][0], bias, X, HW, pix0, va);

    const int tm = threadIdx.x & 31, tn = threadIdx.x >> 5;
    const int n0 = tn * 16;

    if (proj == 0) {
#pragma unroll
        for (int i = 0; i < 4; i++)
#pragma unroll
            for (int c2 = 0; c2 < 16; c2++) va[i][c2] *= QSCALE;
    }

    if (proj < 2) {
        float* dst = ((proj == 0) ? g_q : g_k) + t * NC * HW;
#pragma unroll
        for (int c2 = 0; c2 < 16; c2++)
            *reinterpret_cast<float4*>(&dst[(n0 + c2) * HW + pix0 + tm * 4]) =
                make_float4(va[0][c2], va[1][c2], va[2][c2], va[3][c2]);
    } else {
        int h = n0 >> 5, dd = n0 & 31;
#pragma unroll
        for (int i = 0; i < 4; i++) {
            int pix = pix0 + tm * 4 + i;
            float* vp = &g_vT[((size_t)(t * HEADS + h) * HW + pix) * HD + dd];
#pragma unroll
            for (int j = 0; j < 4; j++)
                *reinterpret_cast<float4*>(&vp[j * 4]) =
                    make_float4(va[i][4 * j], va[i][4 * j + 1], va[i][4 * j + 2], va[i][4 * j + 3]);
        }
    }
}

// ---------------- kernel 4: final projection GEMM ----------------
__global__ __launch_bounds__(256, 2) void proj_kernel(
    const float* __restrict__ pb, float* __restrict__ out)
{
    int q0 = blockIdx.x * 128;
    int t = q0 / HW, hw0 = q0 - t * HW;

    float va[4][16];
    gemm_core(&g_WT[3][0][0], pb, g_att, NQ, q0, va);

    const int tm = threadIdx.x & 31, tn = threadIdx.x >> 5;
    const int n0 = tn * 16;
#pragma unroll
    for (int c2 = 0; c2 < 16; c2++)
        *reinterpret_cast<float4*>(&out[(size_t)(t * NC + n0 + c2) * HW + hw0 + tm * 4]) =
            make_float4(va[0][c2], va[1][c2], va[2][c2], va[3][c2]);
}

// ---------------- kernel 3: non-local attention (chunked top-k, b64 direct loads) ----------------
#define CEA(A, i, j) do { unsigned _a = A[i], _b = A[j]; \
    A[i] = (_a > _b) ? _a : _b; A[j] = (_a > _b) ? _b : _a; } while (0)

#define SORT8A(A, o) do { \
    CEA(A,o+0,o+1); CEA(A,o+2,o+3); CEA(A,o+4,o+5); CEA(A,o+6,o+7); \
    CEA(A,o+0,o+2); CEA(A,o+1,o+3); CEA(A,o+4,o+6); CEA(A,o+5,o+7); \
    CEA(A,o+1,o+2); CEA(A,o+5,o+6); \
    CEA(A,o+0,o+4); CEA(A,o+1,o+5); CEA(A,o+2,o+6); CEA(A,o+3,o+7); \
    CEA(A,o+2,o+4); CEA(A,o+3,o+5); \
    CEA(A,o+1,o+2); CEA(A,o+3,o+4); CEA(A,o+5,o+6); } while (0)

#define BM8A(A, o) do { \
    CEA(A,o+0,o+4); CEA(A,o+1,o+5); CEA(A,o+2,o+6); CEA(A,o+3,o+7); \
    CEA(A,o+0,o+2); CEA(A,o+1,o+3); CEA(A,o+4,o+6); CEA(A,o+5,o+7); \
    CEA(A,o+0,o+1); CEA(A,o+2,o+3); CEA(A,o+4,o+5); CEA(A,o+6,o+7); } while (0)

#define MERGE16A(A) do { \
    CEA(A,0,15); CEA(A,1,14); CEA(A,2,13); CEA(A,3,12); \
    CEA(A,4,11); CEA(A,5,10); CEA(A,6,9);  CEA(A,7,8); \
    BM8A(A,0); BM8A(A,8); } while (0)

#define SORTB16A(A) do { \
    CEA(A,0,8);  CEA(A,1,9);  CEA(A,2,10); CEA(A,3,11); \
    CEA(A,4,12); CEA(A,5,13); CEA(A,6,14); CEA(A,7,15); \
    BM8A(A,0); BM8A(A,8); } while (0)

__global__ __launch_bounds__(256, 2) void attn_kernel()
{
    extern __shared__ float sm[];
    const int tid = threadIdx.x;
    const int tx = tid & 31, ty = tid >> 5;
    const int tcx = (blockIdx.x % 3) * TW, trow = (blockIdx.x / 3) * TH;
    const int h = blockIdx.y, t = blockIdx.z;
    const int base = (t * NC + h * HD) * HW;
    const int br = trow - 4, bc = tcx - 4;

    // stage reflected k halo, d-quads interleaved: float4 [d4][lp]
    for (int idx = tid; idx < 8 * HP; idx += 256) {
        int d4 = idx / HP, lp = idx - d4 * HP;
        int lr = lp / HC, lc = lp - lr * HC;
        int ri = refl(br + lr), rj = refl(bc + lc);
        const float* gp = g_k + base + (d4 * 4) * HW + ri * NW + rj;
        reinterpret_cast<float4*>(sm)[idx] =
            make_float4(gp[0], gp[HW], gp[2 * HW], gp[3 * HW]);
    }
    __syncthreads();

    const int gi = trow + ty, gj = tcx + tx;
    const int pix = gi * NW + gj;

    ull q2[16];
#pragma unroll
    for (int d2 = 0; d2 < 16; d2++)
        q2[d2] = pk2(g_q[base + (2 * d2) * HW + pix], g_q[base + (2 * d2 + 1) * HW + pix]);

    unsigned top[16];
    unsigned mxkey = 0;

#pragma unroll
    for (int ch = 0; ch < 4; ch++) {
        unsigned key[16];
#pragma unroll
        for (int a2 = 0; a2 < 2; a2++) {
            int arow = 2 * ch + a2;
#pragma unroll
            for (int b = 0; b < 8; b++) {
                int lp = (ty + arow) * HC + (tx + b);
                const ulonglong2* kp = reinterpret_cast<const ulonglong2*>(sm) + lp;
                ull s0 = 0ull, s1 = 0ull;
#pragma unroll
                for (int d4 = 0; d4 < 8; d4++) {
                    ulonglong2 kv = kp[d4 * HP];      // direct b64 pair, no pack movs
                    fma2(s0, q2[2 * d4],     kv.x);
                    fma2(s1, q2[2 * d4 + 1], kv.y);
                }
                float x0, x1, y0, y1;
                upk2(s0, x0, x1); upk2(s1, y0, y1);
                float s = (x0 + y0) + (x1 + y1);
                unsigned u = __float_as_uint(s);
                unsigned kk = (u & 0x80000000u) ? ~u : (u | 0x80000000u);
                key[a2 * 8 + b] = (kk & 0xFFFFFFC0u) | (unsigned)(arow * 8 + b);
            }
        }
        SORT8A(key, 0); SORT8A(key, 8);
        MERGE16A(key);
        if (ch == 0) {
            mxkey = key[0];
#pragma unroll
            for (int i = 0; i < 16; i++) top[i] = key[i];
        } else {
            if (key[0] > mxkey) mxkey = key[0];
#pragma unroll
            for (int i = 0; i < 16; i++) {
                unsigned b2 = key[15 - i];
                if (b2 > top[i]) top[i] = b2;
            }
            if (ch < 3) SORTB16A(top);
        }
    }
    __syncthreads();   // all k reads complete before overwrite

    // stage reflected v halo, pixel-major, XOR slot swizzle: float4 [lp][d4^(lp&7)]
    const float* vbase = g_vT + (size_t)(t * HEADS + h) * HW * HD;
    for (int idx = tid; idx < 8 * HP; idx += 256) {
        int lp = idx >> 3, d4 = idx & 7;
        int lr = lp / HC, lc = lp - lr * HC;
        int ri = refl(br + lr), rj = refl(bc + lc);
        float4 vv = *reinterpret_cast<const float4*>(&vbase[(size_t)(ri * NW + rj) * HD + d4 * 4]);
        reinterpret_cast<float4*>(sm)[lp * 8 + (d4 ^ (lp & 7))] = vv;
    }
    __syncthreads();

    unsigned mu = (mxkey & 0x80000000u) ? (mxkey ^ 0x80000000u) : ~mxkey;
    float mxv = __uint_as_float(mu);

    float wgt[16]; int lps[16];
    float wsum = 0.f;
#pragma unroll
    for (int p = 0; p < 16; p++) {
        unsigned kk = top[p];
        int ci = kk & 63;
        unsigned u = (kk & 0x80000000u) ? (kk ^ 0x80000000u) : ~kk;
        float e = __expf(__uint_as_float(u) - mxv);
        wsum += e;
        wgt[p] = e;
        lps[p] = (ty + (ci >> 3)) * HC + (tx + (ci & 7));
    }

    ull acc2[16];
#pragma unroll
    for (int c = 0; c < 16; c++) acc2[c] = 0ull;
#pragma unroll
    for (int p = 0; p < 16; p++) {
        int lp = lps[p];
        const ulonglong2* vp = reinterpret_cast<const ulonglong2*>(sm) + lp * 8;  // 16B units, pixel row = 8 units
        int sw = lp & 7;
        ull e2 = pk2(wgt[p], wgt[p]);
#pragma unroll
        for (int d4 = 0; d4 < 8; d4++) {
            ulonglong2 vv = vp[d4 ^ sw];              // direct b64 pair, no pack movs
            fma2(acc2[2 * d4],     e2, vv.x);
            fma2(acc2[2 * d4 + 1], e2, vv.y);
        }
    }

    float inv = 1.f / wsum;
    const int qg = t * HW + pix;
#pragma unroll
    for (int c = 0; c < 16; c++) {
        float lo, hi;
        upk2(acc2[c], lo, hi);
        g_att[(size_t)(h * HD + 2 * c) * NQ + qg] = lo * inv;
        g_att[(size_t)(h * HD + 2 * c + 1) * NQ + qg] = hi * inv;
    }
}

// ---------------- launch ----------------
extern "C" void kernel_launch(void* const* d_in, const int* in_sizes, int n_in,
                              void* d_out, int out_size)
{
    const float* vid    = (const float*)d_in[0];
    const float* wq_dw  = (const float*)d_in[1];
    const float* wq_pw  = (const float*)d_in[2];
    const float* bq     = (const float*)d_in[3];
    const float* wk_dw  = (const float*)d_in[4];
    const float* wk_pw  = (const float*)d_in[5];
    const float* bk     = (const float*)d_in[6];
    const float* wv_dw  = (const float*)d_in[7];
    const float* wv_pw  = (const float*)d_in[8];
    const float* bv     = (const float*)d_in[9];
    const float* proj_w = (const float*)d_in[10];
    const float* proj_b = (const float*)d_in[11];
    float* out = (float*)d_out;

    const int attn_smem = 8 * HP * 16;                        // 74880
    const int gemm_smem = (NC * NC + 2 * 16 * NC) * (int)sizeof(float);  // 81920
    cudaFuncSetAttribute(attn_kernel, cudaFuncAttributeMaxDynamicSharedMemorySize, attn_smem);
    cudaFuncSetAttribute(pw_kernel, cudaFuncAttributeMaxDynamicSharedMemorySize, gemm_smem);
    cudaFuncSetAttribute(proj_kernel, cudaFuncAttributeMaxDynamicSharedMemorySize, gemm_smem);

    wt_kernel<<<dim3(16, 4), 256>>>(wq_pw, wk_pw, wv_pw, proj_w);
    dw_kernel<<<dim3(9, 2, 16), 256>>>(vid, wq_dw, wk_dw, wv_dw);
    pw_kernel<<<dim3(72, 2, 3), 256, gemm_smem>>>(bq, bk, bv);
    attn_kernel<<<dim3(36, 4, 2), 256, attn_smem>>>();
    proj_kernel<<<dim3(144, 1, 1), 256, gemm_smem>>>(proj_b, out);
}